// round 3
// baseline (speedup 1.0000x reference)
#include <cuda_runtime.h>
#include <cuda_bf16.h>

// Fixed problem shape
#define BATCH 4
#define HEADS 16
#define SEQ   2048
#define DHEAD 64

#define BM 64          // query tile rows
#define BN 64          // key tile cols
#define SSTRIDE 68     // smem row stride (floats) — 68 mod 32 = 4, conflict-aware
#define NEGV (-1000000000.0f)

__global__ __launch_bounds__(256, 2)
void flash_attn_fp32_kernel(const float* __restrict__ Q,
                            const float* __restrict__ K,
                            const float* __restrict__ V,
                            const int* __restrict__ mask,   // bool promoted to int32 by harness
                            float* __restrict__ O)
{
    extern __shared__ float sm[];
    float* Qs = sm;                       // BM x SSTRIDE
    float* Ks = Qs + BM * SSTRIDE;        // BN x SSTRIDE
    float* Vs = Ks + BN * SSTRIDE;        // BN x SSTRIDE
    float* Ps = Vs + BN * SSTRIDE;        // BM x SSTRIDE

    const int tid = threadIdx.x;
    const int tx = tid & 15;              // 16 col-groups
    const int ty = tid >> 4;              // 16 row-groups (4 rows each)

    const int bh = blockIdx.y;            // b*HEADS + h
    const int b  = bh / HEADS;
    const int q0 = blockIdx.x * BM;

    const float* Qp = Q + ((size_t)bh * SEQ + q0) * DHEAD;
    const float* Kp = K + (size_t)bh * SEQ * DHEAD;
    const float* Vp = V + (size_t)bh * SEQ * DHEAD;
    const int*   Mp = mask + (size_t)b * SEQ * SEQ + (size_t)q0 * SEQ;
    float* Op = O + ((size_t)bh * SEQ + q0) * DHEAD;

    // ---- load Q tile (coalesced float4) ----
    for (int i = tid; i < BM * DHEAD / 4; i += 256) {
        int r  = i / (DHEAD / 4);
        int c4 = i % (DHEAD / 4);
        float4 v = ((const float4*)(Qp + (size_t)r * DHEAD))[c4];
        *(float4*)(Qs + r * SSTRIDE + c4 * 4) = v;
    }

    float acc[4][4];
    float mrow[4], lrow[4];
    #pragma unroll
    for (int i = 0; i < 4; i++) {
        mrow[i] = -3.0e38f;
        lrow[i] = 0.0f;
        #pragma unroll
        for (int j = 0; j < 4; j++) acc[i][j] = 0.0f;
    }

    const float scale = 0.125f;  // 1/sqrt(64)

    for (int n0 = 0; n0 < SEQ; n0 += BN) {
        __syncthreads();  // previous iter's P/V consumers done before overwrite
        // ---- load K,V tiles ----
        for (int i = tid; i < BN * DHEAD / 4; i += 256) {
            int r  = i / (DHEAD / 4);
            int c4 = i % (DHEAD / 4);
            float4 kv = ((const float4*)(Kp + (size_t)(n0 + r) * DHEAD))[c4];
            *(float4*)(Ks + r * SSTRIDE + c4 * 4) = kv;
            float4 vv = ((const float4*)(Vp + (size_t)(n0 + r) * DHEAD))[c4];
            *(float4*)(Vs + r * SSTRIDE + c4 * 4) = vv;
        }
        __syncthreads();

        // ---- S = Q K^T (64x64 tile, 4x4 per thread, cols tx+16j) ----
        float s[4][4];
        #pragma unroll
        for (int i = 0; i < 4; i++)
            #pragma unroll
            for (int j = 0; j < 4; j++) s[i][j] = 0.0f;

        #pragma unroll
        for (int d = 0; d < DHEAD; d += 4) {
            float4 q[4], k[4];
            #pragma unroll
            for (int i = 0; i < 4; i++)
                q[i] = *(const float4*)(Qs + (ty * 4 + i) * SSTRIDE + d);
            #pragma unroll
            for (int j = 0; j < 4; j++)
                k[j] = *(const float4*)(Ks + (tx + 16 * j) * SSTRIDE + d);
            #pragma unroll
            for (int i = 0; i < 4; i++)
                #pragma unroll
                for (int j = 0; j < 4; j++)
                    s[i][j] += q[i].x * k[j].x + q[i].y * k[j].y
                             + q[i].z * k[j].z + q[i].w * k[j].w;
        }

        // ---- mask + scale (reference: where(mask, NEG, s) then /sqrt(D)) ----
        #pragma unroll
        for (int i = 0; i < 4; i++) {
            const int* mp = Mp + (size_t)(ty * 4 + i) * SEQ + n0;
            #pragma unroll
            for (int j = 0; j < 4; j++) {
                int mk = mp[tx + 16 * j];
                s[i][j] = mk ? (NEGV * scale) : s[i][j] * scale;
            }
        }

        // ---- online softmax update (row = 16 lanes within a half-warp) ----
        #pragma unroll
        for (int i = 0; i < 4; i++) {
            float mx = fmaxf(fmaxf(s[i][0], s[i][1]), fmaxf(s[i][2], s[i][3]));
            #pragma unroll
            for (int o = 1; o < 16; o <<= 1)
                mx = fmaxf(mx, __shfl_xor_sync(0xffffffffu, mx, o));
            float newm  = fmaxf(mrow[i], mx);
            float alpha = __expf(mrow[i] - newm);
            mrow[i] = newm;
            float rs = 0.0f;
            #pragma unroll
            for (int j = 0; j < 4; j++) {
                s[i][j] = __expf(s[i][j] - newm);
                rs += s[i][j];
            }
            #pragma unroll
            for (int o = 1; o < 16; o <<= 1)
                rs += __shfl_xor_sync(0xffffffffu, rs, o);
            lrow[i] = lrow[i] * alpha + rs;
            #pragma unroll
            for (int j = 0; j < 4; j++) acc[i][j] *= alpha;
        }

        // ---- stage P to smem ----
        #pragma unroll
        for (int i = 0; i < 4; i++)
            #pragma unroll
            for (int j = 0; j < 4; j++)
                Ps[(ty * 4 + i) * SSTRIDE + tx + 16 * j] = s[i][j];
        __syncthreads();

        // ---- O += P V (64x64x64) ----
        #pragma unroll 4
        for (int k = 0; k < BN; k++) {
            float p[4], v[4];
            #pragma unroll
            for (int i = 0; i < 4; i++) p[i] = Ps[(ty * 4 + i) * SSTRIDE + k];
            #pragma unroll
            for (int j = 0; j < 4; j++) v[j] = Vs[k * SSTRIDE + tx + 16 * j];
            #pragma unroll
            for (int i = 0; i < 4; i++)
                #pragma unroll
                for (int j = 0; j < 4; j++)
                    acc[i][j] += p[i] * v[j];
        }
    }

    // ---- normalize + write out ----
    #pragma unroll
    for (int i = 0; i < 4; i++) {
        float inv = 1.0f / lrow[i];
        #pragma unroll
        for (int j = 0; j < 4; j++)
            Op[(size_t)(ty * 4 + i) * DHEAD + tx + 16 * j] = acc[i][j] * inv;
    }
}

extern "C" void kernel_launch(void* const* d_in, const int* in_sizes, int n_in,
                              void* d_out, int out_size)
{
    const float* Q = (const float*)d_in[0];
    const float* K = (const float*)d_in[1];
    const float* V = (const float*)d_in[2];
    const int*   M = (const int*)d_in[3];
    float*       O = (float*)d_out;

    const int smem_bytes = 4 * BM * SSTRIDE * (int)sizeof(float);  // 69632
    cudaFuncSetAttribute(flash_attn_fp32_kernel,
                         cudaFuncAttributeMaxDynamicSharedMemorySize, smem_bytes);

    dim3 grid(SEQ / BM, BATCH * HEADS);  // (32, 64)
    flash_attn_fp32_kernel<<<grid, 256, smem_bytes>>>(Q, K, V, M, O);
}

// round 4
// speedup vs baseline: 3.1148x; 3.1148x over previous
#include <cuda_runtime.h>
#include <cuda_fp16.h>

#define BATCH 4
#define HEADS 16
#define SEQ   2048
#define DHEAD 64
#define NELEM (BATCH*HEADS*SEQ*DHEAD)      // 8388608
#define NMASK (BATCH*SEQ*SEQ)              // 16777216
#define SSTR  72                           // smem half stride per 64-elem row

// -------- device scratch (allowed: static __device__ arrays) --------
__device__ __half g_Qhi[NELEM];
__device__ __half g_Qlo[NELEM];
__device__ __half g_Khi[NELEM];
__device__ __half g_Klo[NELEM];
__device__ __half g_Vh [NELEM];
__device__ unsigned g_mbits[NMASK/32];     // 524288 words = 2MB

// -------- pre-pass: pack mask bits --------
__global__ void pack_mask_kernel(const int* __restrict__ mask)
{
    int warp = (blockIdx.x * blockDim.x + threadIdx.x) >> 5;
    int lane = threadIdx.x & 31;
    size_t base = (size_t)warp * 1024;
    #pragma unroll
    for (int i = 0; i < 32; i++) {
        int v = mask[base + i * 32 + lane];
        unsigned bits = __ballot_sync(0xffffffffu, v != 0);
        if (lane == i) g_mbits[warp * 32 + i] = bits;
    }
}

// -------- pre-pass: split Q,K to hi/lo fp16; V to fp16 --------
__global__ void split_qkv_kernel(const float* __restrict__ Q,
                                 const float* __restrict__ K,
                                 const float* __restrict__ V)
{
    int i = blockIdx.x * blockDim.x + threadIdx.x;
    float q = Q[i];
    __half qh = __float2half_rn(q);
    g_Qhi[i] = qh;
    g_Qlo[i] = __float2half_rn(q - __half2float(qh));
    float k = K[i];
    __half kh = __float2half_rn(k);
    g_Khi[i] = kh;
    g_Klo[i] = __float2half_rn(k - __half2float(kh));
    g_Vh[i] = __float2half_rn(V[i]);
}

// -------- mma / ldmatrix helpers --------
__device__ __forceinline__ void mma16816(float* c, const unsigned* a,
                                         unsigned b0, unsigned b1)
{
    asm volatile(
        "mma.sync.aligned.m16n8k16.row.col.f32.f16.f16.f32 "
        "{%0,%1,%2,%3}, {%4,%5,%6,%7}, {%8,%9}, {%0,%1,%2,%3};\n"
        : "+f"(c[0]), "+f"(c[1]), "+f"(c[2]), "+f"(c[3])
        : "r"(a[0]), "r"(a[1]), "r"(a[2]), "r"(a[3]), "r"(b0), "r"(b1));
}

__device__ __forceinline__ void ldsm4(unsigned* r, const void* p)
{
    unsigned a = (unsigned)__cvta_generic_to_shared(p);
    asm volatile("ldmatrix.sync.aligned.m8n8.x4.shared.b16 {%0,%1,%2,%3}, [%4];"
                 : "=r"(r[0]), "=r"(r[1]), "=r"(r[2]), "=r"(r[3]) : "r"(a));
}

__device__ __forceinline__ void ldsm4t(unsigned* r, const void* p)
{
    unsigned a = (unsigned)__cvta_generic_to_shared(p);
    asm volatile("ldmatrix.sync.aligned.m8n8.x4.trans.shared.b16 {%0,%1,%2,%3}, [%4];"
                 : "=r"(r[0]), "=r"(r[1]), "=r"(r[2]), "=r"(r[3]) : "r"(a));
}

__device__ __forceinline__ unsigned h2u(__half2 h) {
    return *reinterpret_cast<unsigned*>(&h);
}

// -------- main attention kernel --------
__global__ __launch_bounds__(128)
void flash_attn_hmma_kernel(float* __restrict__ O)
{
    __shared__ __align__(16) __half sKhi[64 * SSTR];
    __shared__ __align__(16) __half sKlo[64 * SSTR];
    __shared__ __align__(16) __half sVh [64 * SSTR];

    const int tid  = threadIdx.x;
    const int warp = tid >> 5;
    const int lane = tid & 31;
    const int bh = blockIdx.y;
    const int b  = bh >> 4;           // HEADS=16
    const int q0 = blockIdx.x * 64;

    // ---- stage Q tile (pre-split halves) and build persistent A fragments ----
    {
        const size_t gq = (size_t)(bh * SEQ + q0) * DHEAD;
        #pragma unroll
        for (int i = 0; i < 4; i++) {
            int idx = i * 128 + tid;
            int r = idx >> 3, ch = (idx & 7) * 8;
            *(uint4*)&sKhi[r * SSTR + ch] = *(const uint4*)&g_Qhi[gq + r * DHEAD + ch];
            *(uint4*)&sKlo[r * SSTR + ch] = *(const uint4*)&g_Qlo[gq + r * DHEAD + ch];
        }
    }
    __syncthreads();

    unsigned qh[4][4], ql[4][4];
    {
        int row = warp * 16 + (lane & 15);
        int col = (lane >> 4) * 8;
        #pragma unroll
        for (int kc = 0; kc < 4; kc++) {
            ldsm4(qh[kc], &sKhi[row * SSTR + kc * 16 + col]);
            ldsm4(ql[kc], &sKlo[row * SSTR + kc * 16 + col]);
        }
    }

    float o[8][4];
    #pragma unroll
    for (int i = 0; i < 8; i++)
        #pragma unroll
        for (int j = 0; j < 4; j++) o[i][j] = 0.0f;
    float m0 = -1.0e30f, m1 = -1.0e30f, l0 = 0.0f, l1 = 0.0f;

    const int gr0 = q0 + warp * 16 + (lane >> 2);   // this thread's row 0 (global in seq)
    const unsigned* mrow0 = g_mbits + (size_t)b * (SEQ * (SEQ / 32)) + (size_t)gr0 * (SEQ / 32);
    const unsigned* mrow1 = mrow0 + 8 * (SEQ / 32);
    const int bp = (lane & 3) * 2;

    for (int n0 = 0; n0 < SEQ; n0 += 64) {
        __syncthreads();
        // ---- load K(hi/lo), V tiles ----
        {
            const size_t gb = (size_t)(bh * SEQ + n0) * DHEAD;
            #pragma unroll
            for (int i = 0; i < 4; i++) {
                int idx = i * 128 + tid;
                int r = idx >> 3, ch = (idx & 7) * 8;
                *(uint4*)&sKhi[r * SSTR + ch] = *(const uint4*)&g_Khi[gb + r * DHEAD + ch];
                *(uint4*)&sKlo[r * SSTR + ch] = *(const uint4*)&g_Klo[gb + r * DHEAD + ch];
                *(uint4*)&sVh [r * SSTR + ch] = *(const uint4*)&g_Vh [gb + r * DHEAD + ch];
            }
        }
        __syncthreads();

        // ---- S = Q K^T : 3-term fp16 split, fp32 accum ----
        float s[8][4];
        #pragma unroll
        for (int i = 0; i < 8; i++)
            #pragma unroll
            for (int j = 0; j < 4; j++) s[i][j] = 0.0f;

        #pragma unroll
        for (int nbp = 0; nbp < 4; nbp++) {
            int krow = nbp * 16 + (lane & 15);
            int kcol = (lane >> 4) * 8;
            #pragma unroll
            for (int kc = 0; kc < 4; kc++) {
                unsigned kh[4], kl[4];
                ldsm4(kh, &sKhi[krow * SSTR + kc * 16 + kcol]);
                ldsm4(kl, &sKlo[krow * SSTR + kc * 16 + kcol]);
                mma16816(s[2 * nbp],     qh[kc], kh[0], kh[2]);
                mma16816(s[2 * nbp],     qh[kc], kl[0], kl[2]);
                mma16816(s[2 * nbp],     ql[kc], kh[0], kh[2]);
                mma16816(s[2 * nbp + 1], qh[kc], kh[1], kh[3]);
                mma16816(s[2 * nbp + 1], qh[kc], kl[1], kl[3]);
                mma16816(s[2 * nbp + 1], ql[kc], kh[1], kh[3]);
            }
        }

        // ---- mask + scale ----
        uint2 wA = *(const uint2*)(mrow0 + (n0 >> 5));
        uint2 wB = *(const uint2*)(mrow1 + (n0 >> 5));
        const float SC = 0.125f, NEGM = -1.25e8f;
        #pragma unroll
        for (int sb = 0; sb < 8; sb++) {
            unsigned wr0 = (sb < 4) ? wA.x : wA.y;
            unsigned wr1 = (sb < 4) ? wB.x : wB.y;
            int bit = (sb & 3) * 8 + bp;
            s[sb][0] = ((wr0 >> bit) & 1)       ? NEGM : s[sb][0] * SC;
            s[sb][1] = ((wr0 >> (bit + 1)) & 1) ? NEGM : s[sb][1] * SC;
            s[sb][2] = ((wr1 >> bit) & 1)       ? NEGM : s[sb][2] * SC;
            s[sb][3] = ((wr1 >> (bit + 1)) & 1) ? NEGM : s[sb][3] * SC;
        }

        // ---- online softmax (rows span 4 lanes of a quad) ----
        float mx0 = s[0][0], mx1 = s[0][2];
        #pragma unroll
        for (int sb = 0; sb < 8; sb++) {
            mx0 = fmaxf(mx0, fmaxf(s[sb][0], s[sb][1]));
            mx1 = fmaxf(mx1, fmaxf(s[sb][2], s[sb][3]));
        }
        mx0 = fmaxf(mx0, __shfl_xor_sync(0xffffffffu, mx0, 1));
        mx0 = fmaxf(mx0, __shfl_xor_sync(0xffffffffu, mx0, 2));
        mx1 = fmaxf(mx1, __shfl_xor_sync(0xffffffffu, mx1, 1));
        mx1 = fmaxf(mx1, __shfl_xor_sync(0xffffffffu, mx1, 2));
        float nm0 = fmaxf(m0, mx0), nm1 = fmaxf(m1, mx1);
        float al0 = __expf(m0 - nm0), al1 = __expf(m1 - nm1);
        m0 = nm0; m1 = nm1;

        float rs0 = 0.0f, rs1 = 0.0f;
        #pragma unroll
        for (int sb = 0; sb < 8; sb++) {
            s[sb][0] = __expf(s[sb][0] - nm0); rs0 += s[sb][0];
            s[sb][1] = __expf(s[sb][1] - nm0); rs0 += s[sb][1];
            s[sb][2] = __expf(s[sb][2] - nm1); rs1 += s[sb][2];
            s[sb][3] = __expf(s[sb][3] - nm1); rs1 += s[sb][3];
        }
        rs0 += __shfl_xor_sync(0xffffffffu, rs0, 1);
        rs0 += __shfl_xor_sync(0xffffffffu, rs0, 2);
        rs1 += __shfl_xor_sync(0xffffffffu, rs1, 1);
        rs1 += __shfl_xor_sync(0xffffffffu, rs1, 2);
        l0 = l0 * al0 + rs0;
        l1 = l1 * al1 + rs1;
        #pragma unroll
        for (int db = 0; db < 8; db++) {
            o[db][0] *= al0; o[db][1] *= al0;
            o[db][2] *= al1; o[db][3] *= al1;
        }

        // ---- O += P V : P split hi/lo in registers, V fp16 ----
        #pragma unroll
        for (int kc2 = 0; kc2 < 4; kc2++) {
            int b0i = 2 * kc2, b1i = 2 * kc2 + 1;
            __half2 h0 = __floats2half2_rn(s[b0i][0], s[b0i][1]);
            __half2 h1 = __floats2half2_rn(s[b0i][2], s[b0i][3]);
            __half2 h2 = __floats2half2_rn(s[b1i][0], s[b1i][1]);
            __half2 h3 = __floats2half2_rn(s[b1i][2], s[b1i][3]);
            float2 f0 = __half22float2(h0), f1 = __half22float2(h1);
            float2 f2 = __half22float2(h2), f3 = __half22float2(h3);
            unsigned Ahi[4] = { h2u(h0), h2u(h1), h2u(h2), h2u(h3) };
            unsigned Alo[4] = {
                h2u(__floats2half2_rn(s[b0i][0] - f0.x, s[b0i][1] - f0.y)),
                h2u(__floats2half2_rn(s[b0i][2] - f1.x, s[b0i][3] - f1.y)),
                h2u(__floats2half2_rn(s[b1i][0] - f2.x, s[b1i][1] - f2.y)),
                h2u(__floats2half2_rn(s[b1i][2] - f3.x, s[b1i][3] - f3.y))
            };
            int vrow = kc2 * 16 + (lane & 15);
            int vcol = (lane >> 4) * 8;
            #pragma unroll
            for (int dbp = 0; dbp < 4; dbp++) {
                unsigned v[4];
                ldsm4t(v, &sVh[vrow * SSTR + dbp * 16 + vcol]);
                mma16816(o[2 * dbp],     Ahi, v[0], v[1]);
                mma16816(o[2 * dbp],     Alo, v[0], v[1]);
                mma16816(o[2 * dbp + 1], Ahi, v[2], v[3]);
                mma16816(o[2 * dbp + 1], Alo, v[2], v[3]);
            }
        }
    }

    // ---- normalize + write ----
    float inv0 = 1.0f / l0, inv1 = 1.0f / l1;
    float* Op = O + (size_t)bh * SEQ * DHEAD;
    #pragma unroll
    for (int db = 0; db < 8; db++) {
        int c = db * 8 + bp;
        float2 v0 = { o[db][0] * inv0, o[db][1] * inv0 };
        float2 v1 = { o[db][2] * inv1, o[db][3] * inv1 };
        *(float2*)&Op[(size_t)gr0 * DHEAD + c]       = v0;
        *(float2*)&Op[(size_t)(gr0 + 8) * DHEAD + c] = v1;
    }
}

extern "C" void kernel_launch(void* const* d_in, const int* in_sizes, int n_in,
                              void* d_out, int out_size)
{
    const float* Q = (const float*)d_in[0];
    const float* K = (const float*)d_in[1];
    const float* V = (const float*)d_in[2];
    const int*   M = (const int*)d_in[3];
    float*       O = (float*)d_out;

    pack_mask_kernel<<<NMASK / (32 * 256 / 32) / 32, 256>>>(M);   // 2048 blocks
    split_qkv_kernel<<<NELEM / 256, 256>>>(Q, K, V);
    dim3 grid(SEQ / 64, BATCH * HEADS);
    flash_attn_hmma_kernel<<<grid, 128>>>(O);
}

// round 6
// speedup vs baseline: 4.2258x; 1.3567x over previous
#include <cuda_runtime.h>
#include <cuda_fp16.h>

#define BATCH 4
#define HEADS 16
#define SEQ   2048
#define DHEAD 64
#define NELEM (BATCH*HEADS*SEQ*DHEAD)      // 8388608
#define NMASK (BATCH*SEQ*SEQ)              // 16777216
#define SSTR  72                           // smem half stride per 64-elem row (144B, ldsm conflict-free)
#define TILE_HALFS (64 * SSTR)             // one 64x64 tile (padded)

// -------- device scratch --------
__device__ __half g_Qh [NELEM];
__device__ __half g_Khi[NELEM];
__device__ __half g_Klo[NELEM];
__device__ __half g_Vh [NELEM];
__device__ unsigned g_mbits[NMASK/32];     // 2MB bit-packed mask

// -------- pre-pass: pack mask bits --------
__global__ void pack_mask_kernel(const int* __restrict__ mask)
{
    int warp = (blockIdx.x * blockDim.x + threadIdx.x) >> 5;
    int lane = threadIdx.x & 31;
    size_t base = (size_t)warp * 1024;
    #pragma unroll
    for (int i = 0; i < 32; i++) {
        int v = mask[base + i * 32 + lane];
        unsigned bits = __ballot_sync(0xffffffffu, v != 0);
        if (lane == i) g_mbits[warp * 32 + i] = bits;
    }
}

// -------- pre-pass: Q->fp16, K->hi/lo fp16, V->fp16 (float4 vectorized) --------
__global__ void split_qkv_kernel(const float4* __restrict__ Q,
                                 const float4* __restrict__ K,
                                 const float4* __restrict__ V)
{
    int i = blockIdx.x * blockDim.x + threadIdx.x;   // one float4 per thread
    float4 q = Q[i];
    uint2 qo;
    __half2 q01 = __floats2half2_rn(q.x, q.y);
    __half2 q23 = __floats2half2_rn(q.z, q.w);
    qo.x = *(unsigned*)&q01; qo.y = *(unsigned*)&q23;
    ((uint2*)g_Qh)[i] = qo;

    float4 k = K[i];
    __half2 kh01 = __floats2half2_rn(k.x, k.y);
    __half2 kh23 = __floats2half2_rn(k.z, k.w);
    float2 f01 = __half22float2(kh01), f23 = __half22float2(kh23);
    __half2 kl01 = __floats2half2_rn(k.x - f01.x, k.y - f01.y);
    __half2 kl23 = __floats2half2_rn(k.z - f23.x, k.w - f23.y);
    uint2 kho, klo;
    kho.x = *(unsigned*)&kh01; kho.y = *(unsigned*)&kh23;
    klo.x = *(unsigned*)&kl01; klo.y = *(unsigned*)&kl23;
    ((uint2*)g_Khi)[i] = kho;
    ((uint2*)g_Klo)[i] = klo;

    float4 v = V[i];
    __half2 v01 = __floats2half2_rn(v.x, v.y);
    __half2 v23 = __floats2half2_rn(v.z, v.w);
    uint2 vo;
    vo.x = *(unsigned*)&v01; vo.y = *(unsigned*)&v23;
    ((uint2*)g_Vh)[i] = vo;
}

// -------- helpers --------
__device__ __forceinline__ void mma16816(float* c, const unsigned* a,
                                         unsigned b0, unsigned b1)
{
    asm volatile(
        "mma.sync.aligned.m16n8k16.row.col.f32.f16.f16.f32 "
        "{%0,%1,%2,%3}, {%4,%5,%6,%7}, {%8,%9}, {%0,%1,%2,%3};\n"
        : "+f"(c[0]), "+f"(c[1]), "+f"(c[2]), "+f"(c[3])
        : "r"(a[0]), "r"(a[1]), "r"(a[2]), "r"(a[3]), "r"(b0), "r"(b1));
}

__device__ __forceinline__ void ldsm4(unsigned* r, const void* p)
{
    unsigned a = (unsigned)__cvta_generic_to_shared(p);
    asm volatile("ldmatrix.sync.aligned.m8n8.x4.shared.b16 {%0,%1,%2,%3}, [%4];"
                 : "=r"(r[0]), "=r"(r[1]), "=r"(r[2]), "=r"(r[3]) : "r"(a));
}

__device__ __forceinline__ void ldsm4t(unsigned* r, const void* p)
{
    unsigned a = (unsigned)__cvta_generic_to_shared(p);
    asm volatile("ldmatrix.sync.aligned.m8n8.x4.trans.shared.b16 {%0,%1,%2,%3}, [%4];"
                 : "=r"(r[0]), "=r"(r[1]), "=r"(r[2]), "=r"(r[3]) : "r"(a));
}

__device__ __forceinline__ unsigned h2u(__half2 h) {
    return *reinterpret_cast<unsigned*>(&h);
}

__device__ __forceinline__ void cp16(void* smem_dst, const void* gsrc)
{
    unsigned d = (unsigned)__cvta_generic_to_shared(smem_dst);
    asm volatile("cp.async.ca.shared.global [%0], [%1], 16;\n" :: "r"(d), "l"(gsrc));
}
__device__ __forceinline__ void cp_commit() {
    asm volatile("cp.async.commit_group;\n");
}
template<int N> __device__ __forceinline__ void cp_wait() {
    asm volatile("cp.async.wait_group %0;\n" :: "n"(N));
}

// -------- main attention kernel --------
__global__ __launch_bounds__(128)
void flash_attn_hmma_kernel(float* __restrict__ O)
{
    extern __shared__ __align__(16) __half smbuf[];
    // layout per buffer b in {0,1}: [Khi | Klo | Vh], each TILE_HALFS
    __half* sKhi[2] = { smbuf,                 smbuf + 3 * TILE_HALFS };
    __half* sKlo[2] = { smbuf + TILE_HALFS,    smbuf + 4 * TILE_HALFS };
    __half* sVh [2] = { smbuf + 2 * TILE_HALFS, smbuf + 5 * TILE_HALFS };

    const int tid  = threadIdx.x;
    const int warp = tid >> 5;
    const int lane = tid & 31;
    const int bh = blockIdx.y;
    const int b  = bh >> 4;           // HEADS=16
    const int q0 = blockIdx.x * 64;

    // per-thread tile-copy coordinates (4 chunks of 16B per tile)
    int cr[4], cc[4];
    #pragma unroll
    for (int i = 0; i < 4; i++) {
        int idx = i * 128 + tid;
        cr[i] = idx >> 3;
        cc[i] = (idx & 7) * 8;
    }

    // ---- stage Q tile into buf1 Khi area (cp.async), then K/V tile 0 into buf0 ----
    {
        const size_t gq = (size_t)(bh * SEQ + q0) * DHEAD;
        #pragma unroll
        for (int i = 0; i < 4; i++)
            cp16(&sKhi[1][cr[i] * SSTR + cc[i]], &g_Qh[gq + cr[i] * DHEAD + cc[i]]);
        cp_commit();                                  // group: Q
        const size_t gb = (size_t)bh * SEQ * DHEAD;   // n0 = 0
        #pragma unroll
        for (int i = 0; i < 4; i++) {
            size_t go = gb + cr[i] * DHEAD + cc[i];
            cp16(&sKhi[0][cr[i] * SSTR + cc[i]], &g_Khi[go]);
            cp16(&sKlo[0][cr[i] * SSTR + cc[i]], &g_Klo[go]);
            cp16(&sVh [0][cr[i] * SSTR + cc[i]], &g_Vh [go]);
        }
        cp_commit();                                  // group: KV0
    }

    cp_wait<1>();         // Q staged (KV0 may still be in flight)
    __syncthreads();

    unsigned qh[4][4];
    {
        int row = warp * 16 + (lane & 15);
        int col = (lane >> 4) * 8;
        #pragma unroll
        for (int kc = 0; kc < 4; kc++)
            ldsm4(qh[kc], &sKhi[1][row * SSTR + kc * 16 + col]);
    }
    __syncthreads();      // Q frags extracted; buf1 may be overwritten by prefetch

    float o[8][4];
    #pragma unroll
    for (int i = 0; i < 8; i++)
        #pragma unroll
        for (int j = 0; j < 4; j++) o[i][j] = 0.0f;
    float m0 = -1.0e30f, m1 = -1.0e30f, l0 = 0.0f, l1 = 0.0f;

    const int gr0 = q0 + warp * 16 + (lane >> 2);
    const unsigned* mrow0 = g_mbits + (size_t)b * (SEQ * (SEQ / 32)) + (size_t)gr0 * (SEQ / 32);
    const unsigned* mrow1 = mrow0 + 8 * (SEQ / 32);
    const int bp = (lane & 3) * 2;

    #pragma unroll 1
    for (int t = 0; t < SEQ / 64; t++) {
        const int n0 = t * 64;
        const int cur = t & 1, nxt = cur ^ 1;

        // ---- prefetch next K/V tile into the other buffer ----
        if (t + 1 < SEQ / 64) {
            const size_t gb = (size_t)(bh * SEQ + n0 + 64) * DHEAD;
            #pragma unroll
            for (int i = 0; i < 4; i++) {
                size_t go = gb + cr[i] * DHEAD + cc[i];
                cp16(&sKhi[nxt][cr[i] * SSTR + cc[i]], &g_Khi[go]);
                cp16(&sKlo[nxt][cr[i] * SSTR + cc[i]], &g_Klo[go]);
                cp16(&sVh [nxt][cr[i] * SSTR + cc[i]], &g_Vh [go]);
            }
            cp_commit();
            cp_wait<1>();   // current tile complete
        } else {
            cp_wait<0>();
        }
        __syncthreads();

        // prefetch mask words early (L2 latency hidden behind QK mmas)
        uint2 wA = *(const uint2*)(mrow0 + (n0 >> 5));
        uint2 wB = *(const uint2*)(mrow1 + (n0 >> 5));

        // ---- S = Qhi (Khi + Klo)^T : 2-term split, fp32 accum ----
        float s[8][4];
        #pragma unroll
        for (int i = 0; i < 8; i++)
            #pragma unroll
            for (int j = 0; j < 4; j++) s[i][j] = 0.0f;

        #pragma unroll
        for (int nbp = 0; nbp < 4; nbp++) {
            int krow = nbp * 16 + (lane & 15);
            int kcol = (lane >> 4) * 8;
            #pragma unroll
            for (int kc = 0; kc < 4; kc++) {
                unsigned kh[4], kl[4];
                ldsm4(kh, &sKhi[cur][krow * SSTR + kc * 16 + kcol]);
                ldsm4(kl, &sKlo[cur][krow * SSTR + kc * 16 + kcol]);
                mma16816(s[2 * nbp],     qh[kc], kh[0], kh[2]);
                mma16816(s[2 * nbp],     qh[kc], kl[0], kl[2]);
                mma16816(s[2 * nbp + 1], qh[kc], kh[1], kh[3]);
                mma16816(s[2 * nbp + 1], qh[kc], kl[1], kl[3]);
            }
        }

        // ---- mask + scale ----
        const float SC = 0.125f, NEGM = -1.25e8f;
        #pragma unroll
        for (int sb = 0; sb < 8; sb++) {
            unsigned wr0 = (sb < 4) ? wA.x : wA.y;
            unsigned wr1 = (sb < 4) ? wB.x : wB.y;
            int bit = (sb & 3) * 8 + bp;
            s[sb][0] = ((wr0 >> bit) & 1)       ? NEGM : s[sb][0] * SC;
            s[sb][1] = ((wr0 >> (bit + 1)) & 1) ? NEGM : s[sb][1] * SC;
            s[sb][2] = ((wr1 >> bit) & 1)       ? NEGM : s[sb][2] * SC;
            s[sb][3] = ((wr1 >> (bit + 1)) & 1) ? NEGM : s[sb][3] * SC;
        }

        // ---- online softmax (row = 4 lanes of a quad) ----
        float mx0 = s[0][0], mx1 = s[0][2];
        #pragma unroll
        for (int sb = 0; sb < 8; sb++) {
            mx0 = fmaxf(mx0, fmaxf(s[sb][0], s[sb][1]));
            mx1 = fmaxf(mx1, fmaxf(s[sb][2], s[sb][3]));
        }
        mx0 = fmaxf(mx0, __shfl_xor_sync(0xffffffffu, mx0, 1));
        mx0 = fmaxf(mx0, __shfl_xor_sync(0xffffffffu, mx0, 2));
        mx1 = fmaxf(mx1, __shfl_xor_sync(0xffffffffu, mx1, 1));
        mx1 = fmaxf(mx1, __shfl_xor_sync(0xffffffffu, mx1, 2));
        float nm0 = fmaxf(m0, mx0), nm1 = fmaxf(m1, mx1);
        float al0 = __expf(m0 - nm0), al1 = __expf(m1 - nm1);
        m0 = nm0; m1 = nm1;

        float rs0 = 0.0f, rs1 = 0.0f;
        #pragma unroll
        for (int sb = 0; sb < 8; sb++) {
            s[sb][0] = __expf(s[sb][0] - nm0); rs0 += s[sb][0];
            s[sb][1] = __expf(s[sb][1] - nm0); rs0 += s[sb][1];
            s[sb][2] = __expf(s[sb][2] - nm1); rs1 += s[sb][2];
            s[sb][3] = __expf(s[sb][3] - nm1); rs1 += s[sb][3];
        }
        rs0 += __shfl_xor_sync(0xffffffffu, rs0, 1);
        rs0 += __shfl_xor_sync(0xffffffffu, rs0, 2);
        rs1 += __shfl_xor_sync(0xffffffffu, rs1, 1);
        rs1 += __shfl_xor_sync(0xffffffffu, rs1, 2);
        l0 = l0 * al0 + rs0;
        l1 = l1 * al1 + rs1;
        #pragma unroll
        for (int db = 0; db < 8; db++) {
            o[db][0] *= al0; o[db][1] *= al0;
            o[db][2] *= al1; o[db][3] *= al1;
        }

        // ---- O += P V : P split hi/lo in registers, V fp16 ----
        #pragma unroll
        for (int kc2 = 0; kc2 < 4; kc2++) {
            int b0i = 2 * kc2, b1i = 2 * kc2 + 1;
            __half2 h0 = __floats2half2_rn(s[b0i][0], s[b0i][1]);
            __half2 h1 = __floats2half2_rn(s[b0i][2], s[b0i][3]);
            __half2 h2 = __floats2half2_rn(s[b1i][0], s[b1i][1]);
            __half2 h3 = __floats2half2_rn(s[b1i][2], s[b1i][3]);
            float2 f0 = __half22float2(h0), f1 = __half22float2(h1);
            float2 f2 = __half22float2(h2), f3 = __half22float2(h3);
            unsigned Ahi[4] = { h2u(h0), h2u(h1), h2u(h2), h2u(h3) };
            unsigned Alo[4] = {
                h2u(__floats2half2_rn(s[b0i][0] - f0.x, s[b0i][1] - f0.y)),
                h2u(__floats2half2_rn(s[b0i][2] - f1.x, s[b0i][3] - f1.y)),
                h2u(__floats2half2_rn(s[b1i][0] - f2.x, s[b1i][1] - f2.y)),
                h2u(__floats2half2_rn(s[b1i][2] - f3.x, s[b1i][3] - f3.y))
            };
            int vrow = kc2 * 16 + (lane & 15);
            int vcol = (lane >> 4) * 8;
            #pragma unroll
            for (int dbp = 0; dbp < 4; dbp++) {
                unsigned v[4];
                ldsm4t(v, &sVh[cur][vrow * SSTR + dbp * 16 + vcol]);
                mma16816(o[2 * dbp],     Ahi, v[0], v[1]);
                mma16816(o[2 * dbp],     Alo, v[0], v[1]);
                mma16816(o[2 * dbp + 1], Ahi, v[2], v[3]);
                mma16816(o[2 * dbp + 1], Alo, v[2], v[3]);
            }
        }
        __syncthreads();   // compute done before next iter overwrites 'nxt' buffer
    }

    // ---- normalize + write ----
    float inv0 = 1.0f / l0, inv1 = 1.0f / l1;
    float* Op = O + (size_t)bh * SEQ * DHEAD;
    #pragma unroll
    for (int db = 0; db < 8; db++) {
        int c = db * 8 + bp;
        float2 v0 = { o[db][0] * inv0, o[db][1] * inv0 };
        float2 v1 = { o[db][2] * inv1, o[db][3] * inv1 };
        *(float2*)&Op[(size_t)gr0 * DHEAD + c]       = v0;
        *(float2*)&Op[(size_t)(gr0 + 8) * DHEAD + c] = v1;
    }
}

extern "C" void kernel_launch(void* const* d_in, const int* in_sizes, int n_in,
                              void* d_out, int out_size)
{
    const float* Q = (const float*)d_in[0];
    const float* K = (const float*)d_in[1];
    const float* V = (const float*)d_in[2];
    const int*   M = (const int*)d_in[3];
    float*       O = (float*)d_out;

    pack_mask_kernel<<<2048, 256>>>(M);
    split_qkv_kernel<<<NELEM / 4 / 256, 256>>>((const float4*)Q, (const float4*)K,
                                               (const float4*)V);

    const int smem_bytes = 2 * 3 * TILE_HALFS * (int)sizeof(__half);  // 55296
    cudaFuncSetAttribute(flash_attn_hmma_kernel,
                         cudaFuncAttributeMaxDynamicSharedMemorySize, smem_bytes);
    dim3 grid(SEQ / 64, BATCH * HEADS);
    flash_attn_hmma_kernel<<<grid, 128, smem_bytes>>>(O);
}

// round 7
// speedup vs baseline: 5.0104x; 1.1857x over previous
#include <cuda_runtime.h>
#include <cuda_fp16.h>

#define BATCH 4
#define HEADS 16
#define SEQ   2048
#define DHEAD 64
#define NELEM (BATCH*HEADS*SEQ*DHEAD)      // 8388608
#define NMASK (BATCH*SEQ*SEQ)              // 16777216
#define SSTR  72                           // smem half stride per 64-elem row
#define TILE_HALFS (64 * SSTR)

// -------- device scratch --------
__device__ __half g_Qh [NELEM];            // Q pre-scaled by 0.125*log2(e), fp16
__device__ __half g_Khi[NELEM];
__device__ __half g_Klo[NELEM];
__device__ __half g_Vh [NELEM];
__device__ unsigned g_mbits[NMASK/32];     // 2MB bit-packed mask

#define QSCALE 0.1803368801111204f         // 0.125 * log2(e)
#define NEG2   (-1.803368801e8f)           // -1e9 * 0.125 * log2(e)  (exp2 domain)

// -------- pre-pass: pack mask bits --------
__global__ void pack_mask_kernel(const int* __restrict__ mask)
{
    int warp = (blockIdx.x * blockDim.x + threadIdx.x) >> 5;
    int lane = threadIdx.x & 31;
    size_t base = (size_t)warp * 1024;
    #pragma unroll
    for (int i = 0; i < 32; i++) {
        int v = mask[base + i * 32 + lane];
        unsigned bits = __ballot_sync(0xffffffffu, v != 0);
        if (lane == i) g_mbits[warp * 32 + i] = bits;
    }
}

// -------- pre-pass: Q(scaled)->fp16, K->hi/lo fp16, V->fp16 --------
__global__ void split_qkv_kernel(const float4* __restrict__ Q,
                                 const float4* __restrict__ K,
                                 const float4* __restrict__ V)
{
    int i = blockIdx.x * blockDim.x + threadIdx.x;
    float4 q = Q[i];
    __half2 q01 = __floats2half2_rn(q.x * QSCALE, q.y * QSCALE);
    __half2 q23 = __floats2half2_rn(q.z * QSCALE, q.w * QSCALE);
    uint2 qo = { *(unsigned*)&q01, *(unsigned*)&q23 };
    ((uint2*)g_Qh)[i] = qo;

    float4 k = K[i];
    __half2 kh01 = __floats2half2_rn(k.x, k.y);
    __half2 kh23 = __floats2half2_rn(k.z, k.w);
    float2 f01 = __half22float2(kh01), f23 = __half22float2(kh23);
    __half2 kl01 = __floats2half2_rn(k.x - f01.x, k.y - f01.y);
    __half2 kl23 = __floats2half2_rn(k.z - f23.x, k.w - f23.y);
    uint2 kho = { *(unsigned*)&kh01, *(unsigned*)&kh23 };
    uint2 klo = { *(unsigned*)&kl01, *(unsigned*)&kl23 };
    ((uint2*)g_Khi)[i] = kho;
    ((uint2*)g_Klo)[i] = klo;

    float4 v = V[i];
    __half2 v01 = __floats2half2_rn(v.x, v.y);
    __half2 v23 = __floats2half2_rn(v.z, v.w);
    uint2 vo = { *(unsigned*)&v01, *(unsigned*)&v23 };
    ((uint2*)g_Vh)[i] = vo;
}

// -------- helpers --------
__device__ __forceinline__ void mma16816(float* c, const unsigned* a,
                                         unsigned b0, unsigned b1)
{
    asm volatile(
        "mma.sync.aligned.m16n8k16.row.col.f32.f16.f16.f32 "
        "{%0,%1,%2,%3}, {%4,%5,%6,%7}, {%8,%9}, {%0,%1,%2,%3};\n"
        : "+f"(c[0]), "+f"(c[1]), "+f"(c[2]), "+f"(c[3])
        : "r"(a[0]), "r"(a[1]), "r"(a[2]), "r"(a[3]), "r"(b0), "r"(b1));
}

__device__ __forceinline__ void ldsm4(unsigned* r, const void* p)
{
    unsigned a = (unsigned)__cvta_generic_to_shared(p);
    asm volatile("ldmatrix.sync.aligned.m8n8.x4.shared.b16 {%0,%1,%2,%3}, [%4];"
                 : "=r"(r[0]), "=r"(r[1]), "=r"(r[2]), "=r"(r[3]) : "r"(a));
}

__device__ __forceinline__ void ldsm4t(unsigned* r, const void* p)
{
    unsigned a = (unsigned)__cvta_generic_to_shared(p);
    asm volatile("ldmatrix.sync.aligned.m8n8.x4.trans.shared.b16 {%0,%1,%2,%3}, [%4];"
                 : "=r"(r[0]), "=r"(r[1]), "=r"(r[2]), "=r"(r[3]) : "r"(a));
}

__device__ __forceinline__ unsigned h2u(__half2 h) {
    return *reinterpret_cast<unsigned*>(&h);
}

__device__ __forceinline__ float fexp2(float x) {
    float y;
    asm("ex2.approx.ftz.f32 %0, %1;" : "=f"(y) : "f"(x));
    return y;
}

__device__ __forceinline__ void cp16(void* smem_dst, const void* gsrc)
{
    unsigned d = (unsigned)__cvta_generic_to_shared(smem_dst);
    asm volatile("cp.async.ca.shared.global [%0], [%1], 16;\n" :: "r"(d), "l"(gsrc));
}
__device__ __forceinline__ void cp_commit() {
    asm volatile("cp.async.commit_group;\n");
}
template<int N> __device__ __forceinline__ void cp_wait() {
    asm volatile("cp.async.wait_group %0;\n" :: "n"(N));
}

// -------- main attention kernel --------
__global__ __launch_bounds__(128)
void flash_attn_hmma_kernel(float* __restrict__ O)
{
    extern __shared__ __align__(16) __half smbuf[];
    __half* sKhi[2] = { smbuf,                  smbuf + 3 * TILE_HALFS };
    __half* sKlo[2] = { smbuf + TILE_HALFS,     smbuf + 4 * TILE_HALFS };
    __half* sVh [2] = { smbuf + 2 * TILE_HALFS, smbuf + 5 * TILE_HALFS };

    const int tid  = threadIdx.x;
    const int warp = tid >> 5;
    const int lane = tid & 31;
    const int bh = blockIdx.y;
    const int b  = bh >> 4;
    const int q0 = blockIdx.x * 64;

    int cr[4], cc[4];
    #pragma unroll
    for (int i = 0; i < 4; i++) {
        int idx = i * 128 + tid;
        cr[i] = idx >> 3;
        cc[i] = (idx & 7) * 8;
    }

    // ---- stage Q tile (buf1), then K/V tile 0 (buf0) ----
    {
        const size_t gq = (size_t)(bh * SEQ + q0) * DHEAD;
        #pragma unroll
        for (int i = 0; i < 4; i++)
            cp16(&sKhi[1][cr[i] * SSTR + cc[i]], &g_Qh[gq + cr[i] * DHEAD + cc[i]]);
        cp_commit();
        const size_t gb = (size_t)bh * SEQ * DHEAD;
        #pragma unroll
        for (int i = 0; i < 4; i++) {
            size_t go = gb + cr[i] * DHEAD + cc[i];
            cp16(&sKhi[0][cr[i] * SSTR + cc[i]], &g_Khi[go]);
            cp16(&sKlo[0][cr[i] * SSTR + cc[i]], &g_Klo[go]);
            cp16(&sVh [0][cr[i] * SSTR + cc[i]], &g_Vh [go]);
        }
        cp_commit();
    }

    cp_wait<1>();
    __syncthreads();

    unsigned qh[4][4];
    {
        int row = warp * 16 + (lane & 15);
        int col = (lane >> 4) * 8;
        #pragma unroll
        for (int kc = 0; kc < 4; kc++)
            ldsm4(qh[kc], &sKhi[1][row * SSTR + kc * 16 + col]);
    }
    __syncthreads();

    float o[8][4];
    #pragma unroll
    for (int i = 0; i < 8; i++)
        #pragma unroll
        for (int j = 0; j < 4; j++) o[i][j] = 0.0f;
    float m0 = -1.0e30f, m1 = -1.0e30f, l0 = 0.0f, l1 = 0.0f;

    const int gr0 = q0 + warp * 16 + (lane >> 2);
    const unsigned* mrow0 = g_mbits + (size_t)b * (SEQ * (SEQ / 32)) + (size_t)gr0 * (SEQ / 32);
    const unsigned* mrow1 = mrow0 + 8 * (SEQ / 32);
    const int bp = (lane & 3) * 2;

    #pragma unroll 1
    for (int t = 0; t < SEQ / 64; t++) {
        const int n0 = t * 64;
        const int cur = t & 1, nxt = cur ^ 1;

        if (t + 1 < SEQ / 64) {
            const size_t gb = (size_t)(bh * SEQ + n0 + 64) * DHEAD;
            #pragma unroll
            for (int i = 0; i < 4; i++) {
                size_t go = gb + cr[i] * DHEAD + cc[i];
                cp16(&sKhi[nxt][cr[i] * SSTR + cc[i]], &g_Khi[go]);
                cp16(&sKlo[nxt][cr[i] * SSTR + cc[i]], &g_Klo[go]);
                cp16(&sVh [nxt][cr[i] * SSTR + cc[i]], &g_Vh [go]);
            }
            cp_commit();
            cp_wait<1>();
        } else {
            cp_wait<0>();
        }
        __syncthreads();

        uint2 wA = *(const uint2*)(mrow0 + (n0 >> 5));
        uint2 wB = *(const uint2*)(mrow1 + (n0 >> 5));

        // ---- S = Qs (Khi + Klo)^T, fp32 accum; Q pre-scaled so S is in exp2 domain ----
        float s[8][4];
        #pragma unroll
        for (int i = 0; i < 8; i++)
            #pragma unroll
            for (int j = 0; j < 4; j++) s[i][j] = 0.0f;

        #pragma unroll
        for (int nbp = 0; nbp < 4; nbp++) {
            int krow = nbp * 16 + (lane & 15);
            int kcol = (lane >> 4) * 8;
            #pragma unroll
            for (int kc = 0; kc < 4; kc++) {
                unsigned kh[4], kl[4];
                ldsm4(kh, &sKhi[cur][krow * SSTR + kc * 16 + kcol]);
                ldsm4(kl, &sKlo[cur][krow * SSTR + kc * 16 + kcol]);
                mma16816(s[2 * nbp],     qh[kc], kh[0], kh[2]);
                mma16816(s[2 * nbp],     qh[kc], kl[0], kl[2]);
                mma16816(s[2 * nbp + 1], qh[kc], kh[1], kh[3]);
                mma16816(s[2 * nbp + 1], qh[kc], kl[1], kl[3]);
            }
        }

        // ---- mask (exp2 domain; no scale multiply needed) ----
        #pragma unroll
        for (int sb = 0; sb < 8; sb++) {
            unsigned wr0 = (sb < 4) ? wA.x : wA.y;
            unsigned wr1 = (sb < 4) ? wB.x : wB.y;
            int bit = (sb & 3) * 8 + bp;
            if ((wr0 >> bit) & 1)       s[sb][0] = NEG2;
            if ((wr0 >> (bit + 1)) & 1) s[sb][1] = NEG2;
            if ((wr1 >> bit) & 1)       s[sb][2] = NEG2;
            if ((wr1 >> (bit + 1)) & 1) s[sb][3] = NEG2;
        }

        // ---- online softmax (base-2) ----
        float mx0 = s[0][0], mx1 = s[0][2];
        #pragma unroll
        for (int sb = 0; sb < 8; sb++) {
            mx0 = fmaxf(mx0, fmaxf(s[sb][0], s[sb][1]));
            mx1 = fmaxf(mx1, fmaxf(s[sb][2], s[sb][3]));
        }
        mx0 = fmaxf(mx0, __shfl_xor_sync(0xffffffffu, mx0, 1));
        mx0 = fmaxf(mx0, __shfl_xor_sync(0xffffffffu, mx0, 2));
        mx1 = fmaxf(mx1, __shfl_xor_sync(0xffffffffu, mx1, 1));
        mx1 = fmaxf(mx1, __shfl_xor_sync(0xffffffffu, mx1, 2));
        float nm0 = fmaxf(m0, mx0), nm1 = fmaxf(m1, mx1);
        float al0 = fexp2(m0 - nm0), al1 = fexp2(m1 - nm1);
        m0 = nm0; m1 = nm1;

        float rs0 = 0.0f, rs1 = 0.0f;
        #pragma unroll
        for (int sb = 0; sb < 8; sb++) {
            s[sb][0] = fexp2(s[sb][0] - nm0); rs0 += s[sb][0];
            s[sb][1] = fexp2(s[sb][1] - nm0); rs0 += s[sb][1];
            s[sb][2] = fexp2(s[sb][2] - nm1); rs1 += s[sb][2];
            s[sb][3] = fexp2(s[sb][3] - nm1); rs1 += s[sb][3];
        }
        rs0 += __shfl_xor_sync(0xffffffffu, rs0, 1);
        rs0 += __shfl_xor_sync(0xffffffffu, rs0, 2);
        rs1 += __shfl_xor_sync(0xffffffffu, rs1, 1);
        rs1 += __shfl_xor_sync(0xffffffffu, rs1, 2);
        l0 = l0 * al0 + rs0;
        l1 = l1 * al1 + rs1;
        #pragma unroll
        for (int db = 0; db < 8; db++) {
            o[db][0] *= al0; o[db][1] *= al0;
            o[db][2] *= al1; o[db][3] *= al1;
        }

        // ---- O += P V : single-term fp16 P ----
        #pragma unroll
        for (int kc2 = 0; kc2 < 4; kc2++) {
            int b0i = 2 * kc2, b1i = 2 * kc2 + 1;
            unsigned Ahi[4] = {
                h2u(__floats2half2_rn(s[b0i][0], s[b0i][1])),
                h2u(__floats2half2_rn(s[b0i][2], s[b0i][3])),
                h2u(__floats2half2_rn(s[b1i][0], s[b1i][1])),
                h2u(__floats2half2_rn(s[b1i][2], s[b1i][3]))
            };
            int vrow = kc2 * 16 + (lane & 15);
            int vcol = (lane >> 4) * 8;
            #pragma unroll
            for (int dbp = 0; dbp < 4; dbp++) {
                unsigned v[4];
                ldsm4t(v, &sVh[cur][vrow * SSTR + dbp * 16 + vcol]);
                mma16816(o[2 * dbp],     Ahi, v[0], v[1]);
                mma16816(o[2 * dbp + 1], Ahi, v[2], v[3]);
            }
        }
        __syncthreads();
    }

    // ---- normalize + write ----
    float inv0 = 1.0f / l0, inv1 = 1.0f / l1;
    float* Op = O + (size_t)bh * SEQ * DHEAD;
    #pragma unroll
    for (int db = 0; db < 8; db++) {
        int c = db * 8 + bp;
        float2 v0 = { o[db][0] * inv0, o[db][1] * inv0 };
        float2 v1 = { o[db][2] * inv1, o[db][3] * inv1 };
        *(float2*)&Op[(size_t)gr0 * DHEAD + c]       = v0;
        *(float2*)&Op[(size_t)(gr0 + 8) * DHEAD + c] = v1;
    }
}

extern "C" void kernel_launch(void* const* d_in, const int* in_sizes, int n_in,
                              void* d_out, int out_size)
{
    const float* Q = (const float*)d_in[0];
    const float* K = (const float*)d_in[1];
    const float* V = (const float*)d_in[2];
    const int*   M = (const int*)d_in[3];
    float*       O = (float*)d_out;

    pack_mask_kernel<<<2048, 256>>>(M);
    split_qkv_kernel<<<NELEM / 4 / 256, 256>>>((const float4*)Q, (const float4*)K,
                                               (const float4*)V);

    const int smem_bytes = 2 * 3 * TILE_HALFS * (int)sizeof(__half);  // 55296
    cudaFuncSetAttribute(flash_attn_hmma_kernel,
                         cudaFuncAttributeMaxDynamicSharedMemorySize, smem_bytes);
    dim3 grid(SEQ / 64, BATCH * HEADS);
    flash_attn_hmma_kernel<<<grid, 128, smem_bytes>>>(O);
}